// round 1
// baseline (speedup 1.0000x reference)
#include <cuda_runtime.h>
#include <cuda_bf16.h>
#include <math.h>

// TimeAwareScaledDotProduct: b=4, h=8, L=256, d=64
// energy[q,k] = (Q.K[k] + Q.tmK[q,k]) / sqrt(d) + attn_mask[q,k], padded -> MASK_VAL
// A = softmax_k(energy)
// O[q,d] = sum_k A[q,k] * (V[k,d] + tmV[q,k,d])
// Output buffer: [O (b,h,L,d) | A (b,h,L,L)] flattened (A written only if out_size fits).

#define L_DIM 256
#define D_DIM 64
#define MASK_VAL (-4294967295.0f)   // -2^32 + 1

__global__ __launch_bounds__(256, 4)
void taspd_kernel(const float* __restrict__ Q,
                  const float* __restrict__ K,
                  const float* __restrict__ V,
                  const float* __restrict__ tmK,
                  const float* __restrict__ tmV,
                  const float* __restrict__ attn_mask,
                  const unsigned char* __restrict__ pad_mask,
                  float* __restrict__ O,
                  float* __restrict__ A_out,
                  int H)   // heads (for b index of padding mask)
{
    const int q  = blockIdx.x;          // 0..L-1
    const int bh = blockIdx.y;          // 0..B*H-1
    const int b  = bh / H;

    const int tid  = threadIdx.x;       // 0..255
    const int wid  = tid >> 5;          // 0..7
    const int lane = tid & 31;

    __shared__ float sQ[D_DIM];
    __shared__ float sE[L_DIM];
    __shared__ float sPart[8][D_DIM];
    __shared__ float sRed[8];
    __shared__ float sBcast;

    // ---- load Q row ----
    const long long row_qd = (long long)(bh * L_DIM + q) * D_DIM;
    if (tid < D_DIM) sQ[tid] = Q[row_qd + tid];
    __syncthreads();

    const float q0 = sQ[2 * lane];
    const float q1 = sQ[2 * lane + 1];

    // ---- phase 1: energy row ----
    const long long tmK_row = ((long long)(bh * L_DIM + q)) * L_DIM * D_DIM;  // + k*D + d
    const long long K_base  = (long long)bh * L_DIM * D_DIM;

    #pragma unroll 4
    for (int i = 0; i < 32; i++) {
        const int k = wid * 32 + i;
        const float2 tk = *(const float2*)&tmK[tmK_row + (long long)k * D_DIM + 2 * lane];
        const float2 kk = *(const float2*)&K[K_base + (long long)k * D_DIM + 2 * lane];
        float p = q0 * (tk.x + kk.x) + q1 * (tk.y + kk.y);
        // warp reduce
        p += __shfl_xor_sync(0xffffffffu, p, 16);
        p += __shfl_xor_sync(0xffffffffu, p, 8);
        p += __shfl_xor_sync(0xffffffffu, p, 4);
        p += __shfl_xor_sync(0xffffffffu, p, 2);
        p += __shfl_xor_sync(0xffffffffu, p, 1);
        if (lane == 0) {
            float e = p * 0.125f + attn_mask[q * L_DIM + k];   // /sqrt(64)
            if (pad_mask[b * L_DIM + k]) e = MASK_VAL;
            sE[k] = e;
        }
    }
    __syncthreads();

    // ---- phase 2: softmax over k ----
    // max
    {
        float m = sE[tid];
        m = fmaxf(m, __shfl_xor_sync(0xffffffffu, m, 16));
        m = fmaxf(m, __shfl_xor_sync(0xffffffffu, m, 8));
        m = fmaxf(m, __shfl_xor_sync(0xffffffffu, m, 4));
        m = fmaxf(m, __shfl_xor_sync(0xffffffffu, m, 2));
        m = fmaxf(m, __shfl_xor_sync(0xffffffffu, m, 1));
        if (lane == 0) sRed[wid] = m;
        __syncthreads();
        if (tid == 0) {
            float mm = sRed[0];
            #pragma unroll
            for (int w = 1; w < 8; w++) mm = fmaxf(mm, sRed[w]);
            sBcast = mm;
        }
        __syncthreads();
    }
    const float rowmax = sBcast;
    float e = __expf(sE[tid] - rowmax);
    __syncthreads();   // protect sBcast reuse below
    // sum
    {
        float s = e;
        s += __shfl_xor_sync(0xffffffffu, s, 16);
        s += __shfl_xor_sync(0xffffffffu, s, 8);
        s += __shfl_xor_sync(0xffffffffu, s, 4);
        s += __shfl_xor_sync(0xffffffffu, s, 2);
        s += __shfl_xor_sync(0xffffffffu, s, 1);
        if (lane == 0) sRed[wid] = s;
        __syncthreads();
        if (tid == 0) {
            float ss = 0.f;
            #pragma unroll
            for (int w = 0; w < 8; w++) ss += sRed[w];
            sBcast = 1.0f / ss;
        }
        __syncthreads();
    }
    const float a = e * sBcast;
    sE[tid] = a;
    if (A_out) {
        A_out[((long long)(bh * L_DIM + q)) * L_DIM + tid] = a;
    }
    __syncthreads();

    // ---- phase 3: output row ----
    const long long tmV_row = ((long long)(bh * L_DIM + q)) * L_DIM * D_DIM;
    const long long V_base  = (long long)bh * L_DIM * D_DIM;

    float accx = 0.f, accy = 0.f;
    #pragma unroll 4
    for (int i = 0; i < 32; i++) {
        const int k = wid * 32 + i;
        const float aw = sE[k];
        const float2 tv = *(const float2*)&tmV[tmV_row + (long long)k * D_DIM + 2 * lane];
        const float2 vv = *(const float2*)&V[V_base + (long long)k * D_DIM + 2 * lane];
        accx = fmaf(aw, vv.x + tv.x, accx);
        accy = fmaf(aw, vv.y + tv.y, accy);
    }
    sPart[wid][2 * lane]     = accx;
    sPart[wid][2 * lane + 1] = accy;
    __syncthreads();

    if (tid < D_DIM) {
        float s = 0.f;
        #pragma unroll
        for (int w = 0; w < 8; w++) s += sPart[w][tid];
        O[row_qd + tid] = s;
    }
}

extern "C" void kernel_launch(void* const* d_in, const int* in_sizes, int n_in,
                              void* d_out, int out_size)
{
    const float* Q   = (const float*)d_in[0];
    const float* K   = (const float*)d_in[1];
    const float* V   = (const float*)d_in[2];
    const float* tmK = (const float*)d_in[3];
    const float* tmV = (const float*)d_in[4];
    const float* attn_mask = (const float*)d_in[5];
    const unsigned char* pad_mask = (const unsigned char*)d_in[6];

    // derive dims (L, D compile-time; bh from sizes)
    const int L  = L_DIM;
    const int D  = D_DIM;
    const int BH = in_sizes[0] / (L * D);      // b*h
    const int B  = in_sizes[6] / L;            // padding_mask = (b, L)
    const int H  = BH / B;

    const long long O_elems = (long long)in_sizes[0];
    const long long A_elems = (long long)BH * L * L;

    float* O_out = (float*)d_out;
    float* A_out = ((long long)out_size >= O_elems + A_elems)
                       ? (float*)d_out + O_elems : nullptr;

    dim3 grid(L, BH);
    taspd_kernel<<<grid, 256>>>(Q, K, V, tmK, tmV, attn_mask, pad_mask,
                                O_out, A_out, H);
}